// round 17
// baseline (speedup 1.0000x reference)
#include <cuda_runtime.h>
#include <cuda_fp16.h>
#include <math.h>
#include <stdint.h>

// ---------------------------------------------------------------------------
// Problem constants
// ---------------------------------------------------------------------------
#define MTOK 32768
#define DMODEL 768
#define KVDIM 256
#define QKVDIM 1280   // 768 + 256 + 256
#define HIDDIM 2048
#define HID2 4096     // w1 | w2 merged
#define NB 2
#define NT 64
#define NS 256
#define NH 12
#define NKV 4

// ---------------------------------------------------------------------------
// Scratch (device globals; no allocation allowed)
// ---------------------------------------------------------------------------
__device__ __half g_h   [MTOK * DMODEL];   // rmsnorm1(x) fp16
__device__ __half g_qkvh[MTOK * QKVDIM];   // q|k|v fp16
__device__ __half g_o   [MTOK * DMODEL];   // attn out fp16
__device__ float  g_x1  [MTOK * DMODEL];
__device__ __half g_h2  [MTOK * DMODEL];   // rmsnorm2(x1) fp16
__device__ __half g_u12 [MTOK * HID2];     // u1|u2 fp16
__device__ __half g_u1h [MTOK * HIDDIM];   // gated fp16
// transposed fp16 weights [N, K]
__device__ __half g_wqkvT[QKVDIM * DMODEL];
__device__ __half g_woT  [DMODEL * DMODEL];
__device__ __half g_w12T [HID2 * DMODEL];
__device__ __half g_w3T  [DMODEL * HIDDIM];

// ---------------------------------------------------------------------------
// helpers
// ---------------------------------------------------------------------------
__device__ __forceinline__ void mma_f16(float* c, const uint32_t* a,
                                        const uint32_t* b) {
  asm volatile(
      "mma.sync.aligned.m16n8k16.row.col.f32.f16.f16.f32 "
      "{%0,%1,%2,%3}, {%4,%5,%6,%7}, {%8,%9}, {%0,%1,%2,%3};"
      : "+f"(c[0]), "+f"(c[1]), "+f"(c[2]), "+f"(c[3])
      : "r"(a[0]), "r"(a[1]), "r"(a[2]), "r"(a[3]), "r"(b[0]), "r"(b[1]));
}

__device__ __forceinline__ void cp_async16(uint32_t smem, const void* g) {
  asm volatile("cp.async.cg.shared.global [%0], [%1], 16;" ::"r"(smem), "l"(g));
}

__device__ __forceinline__ void ldsm_x4(uint32_t* r, uint32_t addr) {
  asm volatile(
      "ldmatrix.sync.aligned.m8n8.x4.shared.b16 {%0,%1,%2,%3}, [%4];"
      : "=r"(r[0]), "=r"(r[1]), "=r"(r[2]), "=r"(r[3])
      : "r"(addr));
}

// ---------------------------------------------------------------------------
// Tile transpose helper + merged transpose kernels
// ---------------------------------------------------------------------------
__device__ __forceinline__ void transpose_tile(const float* __restrict__ in,
                                               __half* __restrict__ out,
                                               int K, int N, int bx, int by) {
  __shared__ float tile[32][33];
  int n0 = bx * 32;
  int k0 = by * 32;
  int tx = threadIdx.x & 31;
  int ty = threadIdx.x >> 5;
#pragma unroll
  for (int r = ty; r < 32; r += 8)
    tile[r][tx] = in[(size_t)(k0 + r) * N + n0 + tx];
  __syncthreads();
#pragma unroll
  for (int r = ty; r < 32; r += 8)
    out[(size_t)(n0 + r) * K + k0 + tx] = __float2half(tile[tx][r]);
}

// grid 1536: wq(576) | wk(192) | wv(192) | wo(576)
__global__ __launch_bounds__(256) void transpose_qkvwo_kernel(
    const float* __restrict__ wq, const float* __restrict__ wk,
    const float* __restrict__ wv, const float* __restrict__ wo,
    __half* __restrict__ wqkvT, __half* __restrict__ woT) {
  int bid = blockIdx.x;
  if (bid < 576) {
    transpose_tile(wq, wqkvT, DMODEL, DMODEL, bid % 24, bid / 24);
  } else if (bid < 768) {
    int b = bid - 576;
    transpose_tile(wk, wqkvT + (size_t)DMODEL * DMODEL, DMODEL, KVDIM,
                   b % 8, b / 8);
  } else if (bid < 960) {
    int b = bid - 768;
    transpose_tile(wv, wqkvT + (size_t)(DMODEL + KVDIM) * DMODEL, DMODEL,
                   KVDIM, b % 8, b / 8);
  } else {
    int b = bid - 960;
    transpose_tile(wo, woT, DMODEL, DMODEL, b % 24, b / 24);
  }
}

// grid 4608: w1(1536) | w2(1536) | w3(1536)
__global__ __launch_bounds__(256) void transpose_mlp_kernel(
    const float* __restrict__ w1, const float* __restrict__ w2,
    const float* __restrict__ w3, __half* __restrict__ w12T,
    __half* __restrict__ w3T) {
  int bid = blockIdx.x;
  if (bid < 1536) {
    transpose_tile(w1, w12T, DMODEL, HIDDIM, bid % 64, bid / 64);
  } else if (bid < 3072) {
    int b = bid - 1536;
    transpose_tile(w2, w12T + (size_t)HIDDIM * DMODEL, DMODEL, HIDDIM,
                   b % 64, b / 64);
  } else {
    int b = bid - 3072;
    transpose_tile(w3, w3T, HIDDIM, DMODEL, b % 24, b / 24);
  }
}

// ---------------------------------------------------------------------------
// FP16 tensor-core GEMM: CTA tile 128x256, 8 warps at 64x64 each.
// C[M,N] = A[M,K] @ Bt[N,K]^T (+ R if non-null; R only with float out)
// BK=32, 6-stage cp.async pipeline (184,320 B smem, 1 CTA/SM).
// Fragment traffic per MAC halved vs 32x64 warp tile; 128 indep accumulators
// per warp give the ILP to hide latency at 8 warps/SM.
// ---------------------------------------------------------------------------
#define ROWB 80                        // bytes per smem row (64B data + 16 pad)
#define A_TILE_B (128 * ROWB)          // 10240
#define B_TILE_B (256 * ROWB)          // 20480
#define STAGE_B (A_TILE_B + B_TILE_B)  // 30720
#define STAGES 6
#define GEMM_DSMEM (STAGES * STAGE_B)  // 184320 bytes

template <typename OutT>
__global__ __launch_bounds__(256) void gemm_f16_kernel(
    const __half* __restrict__ A, const __half* __restrict__ Bt,
    const float* __restrict__ R, OutT* __restrict__ C,
    int M, int N, int K) {
  extern __shared__ char sm_raw[];
  const uint32_t sbase = (uint32_t)__cvta_generic_to_shared(sm_raw);

  const int tid = threadIdx.x;
  const int lane = tid & 31;
  const int warp = tid >> 5;
  const int wm = warp & 1;       // 2 warps in M
  const int wn = warp >> 1;      // 4 warps in N
  const int gid = lane >> 2;
  const int tin = lane & 3;
  const int grp = lane >> 3;
  const int l8 = lane & 7;
  const int bx = blockIdx.x;
  const int by = blockIdx.y;

  const __half* Ag = A + (size_t)by * 128 * K;
  const __half* Bg = Bt + (size_t)bx * 256 * K;

  const uint32_t a_lane_off =
      (uint32_t)((wm * 64 + ((grp & 1) << 3) + l8) * ROWB + ((grp >> 1) << 4));
  const uint32_t b_lane_off = (uint32_t)A_TILE_B +
      (uint32_t)((wn * 64 + ((grp >> 1) << 3) + l8) * ROWB + ((grp & 1) << 4));

  float acc[4][8][4];
#pragma unroll
  for (int mi = 0; mi < 4; mi++)
#pragma unroll
    for (int ni = 0; ni < 8; ni++)
#pragma unroll
      for (int f = 0; f < 4; f++) acc[mi][ni][f] = 0.f;

  const int ntiles = K >> 5;

  // stage loader: A 512 chunks, B 1024 chunks of 16B (8 halves); 6/thread
  auto issue = [&](int st, int kt) {
    const uint32_t ab = sbase + (uint32_t)(st * STAGE_B);
    const uint32_t bb = ab + (uint32_t)A_TILE_B;
#pragma unroll
    for (int r = 0; r < 2; r++) {
      int c = tid + r * 256;
      int row = c >> 2;
      int cc = c & 3;
      cp_async16(ab + (uint32_t)(row * ROWB + cc * 16),
                 Ag + (size_t)row * K + kt + cc * 8);
    }
#pragma unroll
    for (int r = 0; r < 4; r++) {
      int c = tid + r * 256;
      int row = c >> 2;
      int cc = c & 3;
      cp_async16(bb + (uint32_t)(row * ROWB + cc * 16),
                 Bg + (size_t)row * K + kt + cc * 8);
    }
  };

  // prologue: 5 tiles in flight
#pragma unroll
  for (int p = 0; p < STAGES - 1; p++) {
    if (p < ntiles) issue(p, p * 32);
    asm volatile("cp.async.commit_group;");
  }

  for (int it = 0; it < ntiles; ++it) {
    asm volatile("cp.async.wait_group %0;" ::"n"(STAGES - 2));
    __syncthreads();
    if (it + STAGES - 1 < ntiles)
      issue((it + STAGES - 1) % STAGES, (it + STAGES - 1) * 32);
    asm volatile("cp.async.commit_group;");

    const uint32_t stage_byte = sbase + (uint32_t)((it % STAGES) * STAGE_B);

#pragma unroll
    for (int ks = 0; ks < 2; ks++) {
      const uint32_t kb = ks * 32;
      uint32_t af[4][4];
#pragma unroll
      for (int mi = 0; mi < 4; mi++)
        ldsm_x4(af[mi],
                stage_byte + a_lane_off + (uint32_t)(mi * 16 * ROWB) + kb);
      uint32_t bf[8][2];
#pragma unroll
      for (int p = 0; p < 4; p++) {
        uint32_t t[4];
        ldsm_x4(t, stage_byte + b_lane_off + (uint32_t)(p * 16 * ROWB) + kb);
        bf[2 * p][0] = t[0];
        bf[2 * p][1] = t[1];
        bf[2 * p + 1][0] = t[2];
        bf[2 * p + 1][1] = t[3];
      }
#pragma unroll
      for (int mi = 0; mi < 4; mi++)
#pragma unroll
        for (int ni = 0; ni < 8; ni++) mma_f16(acc[mi][ni], af[mi], bf[ni]);
    }
  }

  // epilogue
#pragma unroll
  for (int mi = 0; mi < 4; mi++) {
#pragma unroll
    for (int ni = 0; ni < 8; ni++) {
      int row = by * 128 + wm * 64 + mi * 16 + gid;
      int col = bx * 256 + wn * 64 + ni * 8 + (tin << 1);
      size_t o0 = (size_t)row * N + col;
      size_t o1 = (size_t)(row + 8) * N + col;
      float2 v0 = {acc[mi][ni][0], acc[mi][ni][1]};
      float2 v1 = {acc[mi][ni][2], acc[mi][ni][3]};
      if (R) {
        float2 r0 = *(const float2*)(R + o0);
        float2 r1 = *(const float2*)(R + o1);
        v0.x += r0.x; v0.y += r0.y;
        v1.x += r1.x; v1.y += r1.y;
      }
      if (sizeof(OutT) == 2) {
        __half2* c0 = (__half2*)((__half*)C + o0);
        __half2* c1 = (__half2*)((__half*)C + o1);
        *c0 = __floats2half2_rn(v0.x, v0.y);
        *c1 = __floats2half2_rn(v1.x, v1.y);
      } else {
        *(float2*)((float*)C + o0) = v0;
        *(float2*)((float*)C + o1) = v1;
      }
    }
  }
}

// ---------------------------------------------------------------------------
// Row RMSNorm over 768 -> fp16 output
// ---------------------------------------------------------------------------
__global__ __launch_bounds__(256) void rmsnorm_kernel(
    const float* __restrict__ x, const float* __restrict__ w,
    __half* __restrict__ out) {
  const int row = blockIdx.x;
  const float* xr = x + (size_t)row * DMODEL;
  __half* orow = out + (size_t)row * DMODEL;
  const int tid = threadIdx.x;
  float v0 = xr[tid];
  float v1 = xr[tid + 256];
  float v2 = xr[tid + 512];
  float s = v0 * v0 + v1 * v1 + v2 * v2;
#pragma unroll
  for (int off = 16; off > 0; off >>= 1)
    s += __shfl_xor_sync(0xffffffffu, s, off);
  __shared__ float ws[8];
  if ((tid & 31) == 0) ws[tid >> 5] = s;
  __syncthreads();
  float tot = ws[0] + ws[1] + ws[2] + ws[3] + ws[4] + ws[5] + ws[6] + ws[7];
  float rs = rsqrtf(tot * (1.0f / (float)DMODEL) + 1e-6f);
  orow[tid]       = __float2half(v0 * rs * w[tid]);
  orow[tid + 256] = __float2half(v1 * rs * w[tid + 256]);
  orow[tid + 512] = __float2half(v2 * rs * w[tid + 512]);
}

// ---------------------------------------------------------------------------
// Attention with fused QK-norm, float4-vectorized smem access.
// ---------------------------------------------------------------------------
#define AST 72
__global__ __launch_bounds__(256) void attn_kernel(
    const __half* __restrict__ qkv, const float* __restrict__ qn,
    const float* __restrict__ kn, __half* __restrict__ o) {
  __shared__ float Qs[64][AST];
  __shared__ float Ks[64][AST];
  const int idx = blockIdx.x;
  const int h = idx % NH;
  const int s = (idx / NH) % NS;
  const int b = idx / (NH * NS);
  const int kvh = h / (NH / NKV);
  const int tid = threadIdx.x;

  for (int i = tid; i < 64 * 64; i += 256) {
    int t = i >> 6, d = i & 63;
    size_t tok = (size_t)((b * NT + t) * NS + s);
    Qs[t][d] = __half2float(qkv[tok * QKVDIM + h * 64 + d]);
    Ks[t][d] = __half2float(qkv[tok * QKVDIM + DMODEL + kvh * 64 + d]);
  }
  __syncthreads();

  const int row = tid >> 2;
  const int tj  = tid & 3;

  {
    float sq = 0.f, sk = 0.f;
#pragma unroll
    for (int jj = 0; jj < 16; jj++) {
      float a = Qs[row][tj * 16 + jj];
      float c = Ks[row][tj * 16 + jj];
      sq += a * a;
      sk += c * c;
    }
    sq += __shfl_xor_sync(0xffffffffu, sq, 1);
    sq += __shfl_xor_sync(0xffffffffu, sq, 2);
    sk += __shfl_xor_sync(0xffffffffu, sk, 1);
    sk += __shfl_xor_sync(0xffffffffu, sk, 2);
    float rq = rsqrtf(sq * (1.0f / 64.0f) + 1e-6f);
    float rk = rsqrtf(sk * (1.0f / 64.0f) + 1e-6f);
#pragma unroll
    for (int jj = 0; jj < 16; jj++) {
      int d = tj * 16 + jj;
      Qs[row][d] *= rq * qn[d];
      Ks[row][d] *= rk * kn[d];
    }
  }
  __syncthreads();

  float lg[16];
#pragma unroll
  for (int jj = 0; jj < 16; jj++) lg[jj] = 0.f;
#pragma unroll 4
  for (int d4 = 0; d4 < 16; d4++) {
    float4 qv = *(const float4*)&Qs[row][d4 * 4];
#pragma unroll
    for (int jj = 0; jj < 16; jj++) {
      int j = jj * 4 + tj;
      float4 kv = *(const float4*)&Ks[j][d4 * 4];
      lg[jj] += qv.x * kv.x + qv.y * kv.y + qv.z * kv.z + qv.w * kv.w;
    }
  }
#pragma unroll
  for (int jj = 0; jj < 16; jj++) {
    int j = jj * 4 + tj;
    float acc = lg[jj] * 0.125f;
    acc = 50.0f * tanhf(acc * 0.02f);
    lg[jj] = (j <= row) ? acc : -INFINITY;
  }

  float mx = lg[0];
#pragma unroll
  for (int jj = 1; jj < 16; jj++) mx = fmaxf(mx, lg[jj]);
  mx = fmaxf(mx, __shfl_xor_sync(0xffffffffu, mx, 1));
  mx = fmaxf(mx, __shfl_xor_sync(0xffffffffu, mx, 2));
  float sum = 0.f;
#pragma unroll
  for (int jj = 0; jj < 16; jj++) {
    float e = __expf(lg[jj] - mx);
    lg[jj] = e;
    sum += e;
  }
  sum += __shfl_xor_sync(0xffffffffu, sum, 1);
  sum += __shfl_xor_sync(0xffffffffu, sum, 2);
  float inv = 1.0f / sum;

  __syncthreads();
#pragma unroll
  for (int jj = 0; jj < 16; jj++) Qs[row][jj * 4 + tj] = lg[jj] * inv;
  for (int i = tid; i < 64 * 64; i += 256) {
    int t = i >> 6, d = i & 63;
    size_t tok = (size_t)((b * NT + t) * NS + s);
    Ks[t][d] = __half2float(qkv[tok * QKVDIM + DMODEL + KVDIM + kvh * 64 + d]);
  }
  __syncthreads();

  float4 acc4[4];
#pragma unroll
  for (int d4 = 0; d4 < 4; d4++) acc4[d4] = make_float4(0.f, 0.f, 0.f, 0.f);
  for (int j = 0; j < 64; j++) {
    float p = Qs[row][j];
#pragma unroll
    for (int d4 = 0; d4 < 4; d4++) {
      float4 kv = *(const float4*)&Ks[j][d4 * 16 + tj * 4];
      acc4[d4].x += p * kv.x;
      acc4[d4].y += p * kv.y;
      acc4[d4].z += p * kv.z;
      acc4[d4].w += p * kv.w;
    }
  }
  size_t tok = (size_t)((b * NT + row) * NS + s);
  __half* obase = o + tok * DMODEL + h * 64;
#pragma unroll
  for (int d4 = 0; d4 < 4; d4++) {
    __half2* dst = (__half2*)(obase + d4 * 16 + tj * 4);
    dst[0] = __floats2half2_rn(acc4[d4].x, acc4[d4].y);
    dst[1] = __floats2half2_rn(acc4[d4].z, acc4[d4].w);
  }
}

// ---------------------------------------------------------------------------
// SwiGLU gate on fp16 merged buffer
// ---------------------------------------------------------------------------
__global__ __launch_bounds__(256) void swiglu_kernel(
    const __half* __restrict__ u12, __half* __restrict__ u1h) {
  size_t idx = (size_t)blockIdx.x * 256 + threadIdx.x;
  size_t c4 = idx * 4;
  size_t r = c4 >> 11;
  size_t c = c4 & 2047;
  const __half2* pa = (const __half2*)(u12 + r * HID2 + c);
  const __half2* pb = (const __half2*)(u12 + r * HID2 + HIDDIM + c);
  float2 a01 = __half22float2(pa[0]);
  float2 a23 = __half22float2(pa[1]);
  float2 b01 = __half22float2(pb[0]);
  float2 b23 = __half22float2(pb[1]);
  float r0 = a01.x / (1.f + __expf(-a01.x)) * b01.x;
  float r1 = a01.y / (1.f + __expf(-a01.y)) * b01.y;
  float r2 = a23.x / (1.f + __expf(-a23.x)) * b23.x;
  float r3 = a23.y / (1.f + __expf(-a23.y)) * b23.y;
  __half2* dst = (__half2*)(u1h + r * HIDDIM + c);
  dst[0] = __floats2half2_rn(r0, r1);
  dst[1] = __floats2half2_rn(r2, r3);
}

// ---------------------------------------------------------------------------
// Launch
// ---------------------------------------------------------------------------
extern "C" void kernel_launch(void* const* d_in, const int* in_sizes, int n_in,
                              void* d_out, int out_size) {
  const float* x  = (const float*)d_in[0];
  const float* n1 = (const float*)d_in[1];
  const float* n2 = (const float*)d_in[2];
  const float* qn = (const float*)d_in[3];
  const float* kn = (const float*)d_in[4];
  const float* wq = (const float*)d_in[5];
  const float* wk = (const float*)d_in[6];
  const float* wv = (const float*)d_in[7];
  const float* wo = (const float*)d_in[8];
  const float* w1 = (const float*)d_in[9];
  const float* w2 = (const float*)d_in[10];
  const float* w3 = (const float*)d_in[11];
  float* out = (float*)d_out;

  __half *h, *qkvh, *o, *h2, *u12, *u1h;
  float *x1;
  __half *wqkvT, *woT, *w12T, *w3T;
  cudaGetSymbolAddress((void**)&h,     g_h);
  cudaGetSymbolAddress((void**)&qkvh,  g_qkvh);
  cudaGetSymbolAddress((void**)&o,     g_o);
  cudaGetSymbolAddress((void**)&x1,    g_x1);
  cudaGetSymbolAddress((void**)&h2,    g_h2);
  cudaGetSymbolAddress((void**)&u12,   g_u12);
  cudaGetSymbolAddress((void**)&u1h,   g_u1h);
  cudaGetSymbolAddress((void**)&wqkvT, g_wqkvT);
  cudaGetSymbolAddress((void**)&woT,   g_woT);
  cudaGetSymbolAddress((void**)&w12T,  g_w12T);
  cudaGetSymbolAddress((void**)&w3T,   g_w3T);

  static bool attr_set = false;
  if (!attr_set) {
    cudaFuncSetAttribute(gemm_f16_kernel<float>,
                         cudaFuncAttributeMaxDynamicSharedMemorySize,
                         GEMM_DSMEM);
    cudaFuncSetAttribute(gemm_f16_kernel<__half>,
                         cudaFuncAttributeMaxDynamicSharedMemorySize,
                         GEMM_DSMEM);
    attr_set = true;
  }

  // launches 1-2: merged weight transposes
  transpose_qkvwo_kernel<<<1536, 256>>>(wq, wk, wv, wo, wqkvT, woT);
  transpose_mlp_kernel<<<4608, 256>>>(w1, w2, w3, w12T, w3T);

  // launch 3: h = rmsnorm(x)  (fp16)
  rmsnorm_kernel<<<MTOK, 256>>>(x, n1, h);

  // launch 4: merged QKV projection  [MTOK,1280] fp16
  gemm_f16_kernel<__half><<<dim3(QKVDIM / 256, MTOK / 128), 256, GEMM_DSMEM>>>(
      h, wqkvT, nullptr, qkvh, MTOK, QKVDIM, DMODEL);

  // launch 5: attention with fused QK-norm (fp16 out)
  attn_kernel<<<NB * NS * NH, 256>>>(qkvh, qn, kn, o);

  // launch 6 (ncu -s 5 -c 1 target): x1 = x + o @ wo  (fp32 out)
  gemm_f16_kernel<float><<<dim3(DMODEL / 256, MTOK / 128), 256, GEMM_DSMEM>>>(
      o, woT, x, x1, MTOK, DMODEL, DMODEL);

  // launch 7: h2 = rmsnorm(x1) (fp16)
  rmsnorm_kernel<<<MTOK, 256>>>(x1, n2, h2);

  // launch 8: merged MLP up projection  [MTOK,4096] fp16
  gemm_f16_kernel<__half><<<dim3(HID2 / 256, MTOK / 128), 256, GEMM_DSMEM>>>(
      h2, w12T, nullptr, u12, MTOK, HID2, DMODEL);

  // launch 9: gate (fp16 out)
  swiglu_kernel<<<(MTOK * HIDDIM) / (256 * 4), 256>>>(u12, u1h);

  // launch 10: out = x1 + u1h @ w3  (fp32 out)
  gemm_f16_kernel<float><<<dim3(DMODEL / 256, MTOK / 128), 256, GEMM_DSMEM>>>(
      u1h, w3T, x1, out, MTOK, DMODEL, HIDDIM);
}